// round 2
// baseline (speedup 1.0000x reference)
#include <cuda_runtime.h>
#include <cuda_bf16.h>

// Problem constants
#define NN   8
#define CC   256
#define HH   64
#define WW   64
#define OC   256
#define KK   9       // 3x3
#define OHW  64      // OUT_H == OUT_W == 64
#define PIX  (OHW*OHW)   // 4096 spatial positions per image

// Scratch (module-scope device arrays; no runtime allocation)
__device__ float g_xt[NN * PIX * CC];     // x transposed to NHWC: [n][h][w][c]
__device__ float g_wt[KK * CC * OC];      // weight transposed to [k][c][oc]

// ---------------------------------------------------------------------------
// Kernel 1: NCHW -> NHWC transpose of input (tiled, conflict-free)
// grid (128, 8, 8) = (pix/32, c/32, n), block (32, 32)
// ---------------------------------------------------------------------------
__global__ void k_transpose_x(const float* __restrict__ x)
{
    __shared__ float tile[32][33];
    const int n  = blockIdx.z;
    const int p0 = blockIdx.x * 32;   // pixel tile
    const int c0 = blockIdx.y * 32;   // channel tile
    const int tx = threadIdx.x, ty = threadIdx.y;

    // coalesced read along pixels
    tile[ty][tx] = x[((size_t)n * CC + (c0 + ty)) * PIX + (p0 + tx)];
    __syncthreads();
    // coalesced write along channels
    g_xt[((size_t)n * PIX + (p0 + ty)) * CC + (c0 + tx)] = tile[tx][ty];
}

// ---------------------------------------------------------------------------
// Kernel 2: weight [oc][c][k] -> [k][c][oc]
// ---------------------------------------------------------------------------
__global__ void k_transpose_w(const float* __restrict__ w)
{
    int idx = blockIdx.x * 256 + threadIdx.x;   // idx over k*C*OC, oc fastest
    int oc = idx & 255;
    int c  = (idx >> 8) & 255;
    int k  = idx >> 16;
    g_wt[idx] = w[((size_t)oc * CC + c) * KK + k];
}

// ---------------------------------------------------------------------------
// Kernel 3: fused deformable gather + SGEMM
// Block tile: BM=64 spatial positions, BN=256 out-channels, BK=32 channels.
// 256 threads, each computes a 4x16 register tile.
// Thread (tx = tid&15, ty = tid>>4):
//   m  = ty*4 + i            (i in 0..3)
//   oc = (j>>2)*64 + tx*4 + (j&3)   (j in 0..15)  -> conflict-free Bs reads
// grid (PIX/64, N) = (64, 8)
// ---------------------------------------------------------------------------
#define BSPITCH 260   // Bs row pitch in floats (1040 B, 16B-aligned, reduces
                      // bank conflicts for the staged output read-out)

__global__ __launch_bounds__(256, 2)
void k_dconv_main(const float* __restrict__ offset, float* __restrict__ out)
{
    __shared__ float As[32][68];         // [BK][BM+pad]
    __shared__ float Bs[32][BSPITCH];    // [BK][BN(+pad)]; reused as output stage
    __shared__ float gw[4][64];          // bilinear corner weights per m
    __shared__ int   gb[4][64];          // corner base offsets into g_xt

    const int tid = threadIdx.x;
    const int tx  = tid & 15;
    const int ty  = tid >> 4;
    const int n   = blockIdx.y;
    const int mb  = blockIdx.x * 64;

    float acc[4][16];
#pragma unroll
    for (int i = 0; i < 4; ++i)
#pragma unroll
        for (int j = 0; j < 16; ++j) acc[i][j] = 0.0f;

    for (int k = 0; k < KK; ++k) {
        // --- precompute bilinear params for the 64 positions of this tile ---
        if (tid < 64) {
            int pos = mb + tid;
            int oh = pos >> 6, ow = pos & 63;
            const float* offp = offset + (((size_t)n * 18 + 2 * k) * OHW + oh) * OHW + ow;
            float offy = offp[0];
            float offx = offp[PIX];       // channel 2k+1 is one plane later
            int ky = k / 3, kx = k % 3;
            float y  = (float)(oh + ky - 1) + offy;
            float xx = (float)(ow + kx - 1) + offx;
            float y0 = floorf(y), x0 = floorf(xx);
#pragma unroll
            for (int d = 0; d < 4; ++d) {
                float yi = y0 + (float)(d >> 1);
                float xi = x0 + (float)(d & 1);
                float wv = (1.0f - fabsf(y - yi)) * (1.0f - fabsf(xx - xi));
                bool valid = (yi >= 0.0f) && (yi <= 63.0f) && (xi >= 0.0f) && (xi <= 63.0f);
                float ycf = fminf(fmaxf(yi, 0.0f), 63.0f);
                float xcf = fminf(fmaxf(xi, 0.0f), 63.0f);
                int yc = (int)ycf, xc = (int)xcf;
                gw[d][tid] = valid ? wv : 0.0f;
                gb[d][tid] = ((n * HH + yc) * WW + xc) * CC;
            }
        }
        __syncthreads();

        for (int c0 = 0; c0 < CC; c0 += 32) {
            // --- build A tile: bilinear gather, coalesced float4 along c ---
#pragma unroll
            for (int p = 0; p < 2; ++p) {
                int m  = (tid >> 3) + p * 32;           // 0..63
                int cc = (tid & 7) * 4;                 // 0..28
                const float* b0 = g_xt + gb[0][m] + c0 + cc;
                const float* b1 = g_xt + gb[1][m] + c0 + cc;
                const float* b2 = g_xt + gb[2][m] + c0 + cc;
                const float* b3 = g_xt + gb[3][m] + c0 + cc;
                float4 v0 = *(const float4*)b0;
                float4 v1 = *(const float4*)b1;
                float4 v2 = *(const float4*)b2;
                float4 v3 = *(const float4*)b3;
                float w0 = gw[0][m], w1 = gw[1][m], w2 = gw[2][m], w3 = gw[3][m];
                As[cc + 0][m] = w0 * v0.x + w1 * v1.x + w2 * v2.x + w3 * v3.x;
                As[cc + 1][m] = w0 * v0.y + w1 * v1.y + w2 * v2.y + w3 * v3.y;
                As[cc + 2][m] = w0 * v0.z + w1 * v1.z + w2 * v2.z + w3 * v3.z;
                As[cc + 3][m] = w0 * v0.w + w1 * v1.w + w2 * v2.w + w3 * v3.w;
            }
            // --- load B tile (weights, L2-resident) ---
            const float* wp = g_wt + ((size_t)k * CC + c0) * OC;
#pragma unroll
            for (int p = 0; p < 8; ++p) {
                int idx = p * 256 + tid;      // over 2048 float4
                int oc4 = idx & 63;
                int cc  = idx >> 6;           // 0..31
                *(float4*)&Bs[cc][oc4 * 4] = *(const float4*)(wp + cc * 256 + oc4 * 4);
            }
            __syncthreads();

            // --- inner GEMM: 4x16 per thread, conflict-free LDS ---
#pragma unroll
            for (int kk = 0; kk < 32; ++kk) {
                float4 a  = *(const float4*)&As[kk][ty * 4];
                float4 b0 = *(const float4*)&Bs[kk][tx * 4 + 0];
                float4 b1 = *(const float4*)&Bs[kk][tx * 4 + 64];
                float4 b2 = *(const float4*)&Bs[kk][tx * 4 + 128];
                float4 b3 = *(const float4*)&Bs[kk][tx * 4 + 192];
                float av[4] = {a.x, a.y, a.z, a.w};
                float bv[16] = {b0.x, b0.y, b0.z, b0.w, b1.x, b1.y, b1.z, b1.w,
                                b2.x, b2.y, b2.z, b2.w, b3.x, b3.y, b3.z, b3.w};
#pragma unroll
                for (int i = 0; i < 4; ++i)
#pragma unroll
                    for (int j = 0; j < 16; ++j)
                        acc[i][j] += av[i] * bv[j];
            }
            __syncthreads();
        }
    }

    // --- coalesced output via shared staging (two 32-row halves) ---
#pragma unroll
    for (int half = 0; half < 2; ++half) {
        __syncthreads();
        if ((ty >> 3) == half) {
            int ml = (ty & 7) * 4;
#pragma unroll
            for (int i = 0; i < 4; ++i)
#pragma unroll
                for (int j = 0; j < 16; ++j) {
                    int oc = (j >> 2) * 64 + tx * 4 + (j & 3);
                    Bs[ml + i][oc] = acc[i][j];
                }
        }
        __syncthreads();
        int p   = tid & 31;       // position within half-tile (lane-contiguous)
        int oc0 = tid >> 5;       // 0..7
        float* ob = out + (size_t)n * OC * PIX + mb + half * 32 + p;
#pragma unroll
        for (int it = 0; it < 32; ++it) {
            int oc = oc0 * 32 + it;
            ob[(size_t)oc * PIX] = Bs[p][oc];
        }
    }
}

// ---------------------------------------------------------------------------
extern "C" void kernel_launch(void* const* d_in, const int* in_sizes, int n_in,
                              void* d_out, int out_size)
{
    const float* x      = (const float*)d_in[0];   // (8,256,64,64)
    const float* offset = (const float*)d_in[1];   // (8,18,64,64)
    const float* weight = (const float*)d_in[2];   // (256,256,3,3)
    float* out = (float*)d_out;                    // (8,256,64,64)

    k_transpose_x<<<dim3(PIX / 32, CC / 32, NN), dim3(32, 32)>>>(x);
    k_transpose_w<<<(KK * CC * OC) / 256, 256>>>(weight);
    k_dconv_main<<<dim3(PIX / 64, NN), 256>>>(offset, out);
}

// round 4
// speedup vs baseline: 1.2149x; 1.2149x over previous
#include <cuda_runtime.h>
#include <cstdint>

// Problem constants
#define NN   8
#define CC   256
#define HH   64
#define WW   64
#define OC   256
#define KK   9
#define OHW  64
#define PIX  4096

// Scratch
__device__ float g_xt[NN * PIX * CC];    // x as NHWC [n][h][w][c]
__device__ float g_wt2[KK * OC * CC];    // weights as [k][oc][c], pre-rounded tf32

__device__ __forceinline__ uint32_t f2tf32(float x) {
    uint32_t r;
    asm("cvt.rna.tf32.f32 %0, %1;" : "=r"(r) : "f"(x));
    return r;
}

// ---------------------------------------------------------------------------
// Kernel 1: NCHW -> NHWC transpose of input
// ---------------------------------------------------------------------------
__global__ void k_transpose_x(const float* __restrict__ x)
{
    __shared__ float tile[32][33];
    const int n  = blockIdx.z;
    const int p0 = blockIdx.x * 32;
    const int c0 = blockIdx.y * 32;
    const int tx = threadIdx.x, ty = threadIdx.y;
    tile[ty][tx] = x[((size_t)n * CC + (c0 + ty)) * PIX + (p0 + tx)];
    __syncthreads();
    g_xt[((size_t)n * PIX + (p0 + ty)) * CC + (c0 + tx)] = tile[tx][ty];
}

// ---------------------------------------------------------------------------
// Kernel 2: weight [oc][c][k] -> [k][oc][c], rounded to tf32
// ---------------------------------------------------------------------------
__global__ void k_transpose_w(const float* __restrict__ w)
{
    int idx = blockIdx.x * 256 + threadIdx.x;   // over k*OC*CC, c fastest
    int c  = idx & 255;
    int oc = (idx >> 8) & 255;
    int k  = idx >> 16;
    g_wt2[idx] = __uint_as_float(f2tf32(w[((size_t)oc * CC + c) * KK + k]));
}

// ---------------------------------------------------------------------------
// Kernel 3: fused deformable gather + tf32 mma.sync GEMM
// CTA tile: M=128 pix, N=128 oc, BK=32.  8 warps: 4(M) x 2(N), warp 32x64.
// Smem rows stride 36 floats (conflict-free fragment loads).
// grid 512 = 8 n * 32 mtiles * 2 ntiles, 256 threads.
// ---------------------------------------------------------------------------
#define ROWP   36                     // smem row pitch (floats)
#define TILEF  (128 * ROWP)           // 4608 floats per tile buffer
#define NCHUNK 72

struct GatherState {
    float wgt[4][4];
    int   gofs[4][4];
};

__device__ __forceinline__ void build_tiles(
    int i, int tid, int n, int mb, int ocb,
    const float* __restrict__ offset,
    float* __restrict__ As, float* __restrict__ Bs,
    GatherState& gs)
{
    const int k  = i >> 3;
    const int c0 = (i & 7) << 5;

    if ((i & 7) == 0) {
        const int ky = k / 3 - 1, kx = k - (k / 3) * 3 - 1;
        const float* offbase = offset + (size_t)(n * 18 + 2 * k) * PIX + mb;
#pragma unroll
        for (int r = 0; r < 4; ++r) {
            int p  = (tid >> 3) + (r << 5);
            int oh = (mb + p) >> 6, ow = (mb + p) & 63;
            float y  = (float)(oh + ky) + offbase[p];
            float xx = (float)(ow + kx) + offbase[p + PIX];
            float y0 = floorf(y), x0 = floorf(xx);
#pragma unroll
            for (int d = 0; d < 4; ++d) {
                float yi = y0 + (float)(d >> 1);
                float xi = x0 + (float)(d & 1);
                float wv = (1.0f - fabsf(y - yi)) * (1.0f - fabsf(xx - xi));
                bool valid = (yi >= 0.0f) && (yi <= 63.0f) &&
                             (xi >= 0.0f) && (xi <= 63.0f);
                int yc = (int)fminf(fmaxf(yi, 0.0f), 63.0f);
                int xc = (int)fminf(fmaxf(xi, 0.0f), 63.0f);
                gs.wgt[r][d]  = valid ? wv : 0.0f;
                gs.gofs[r][d] = ((n * HH + yc) * WW + xc) << 8;
            }
        }
    }

    // A tile: bilinear gather + tf32 convert. 128 pix x 32 c.
    const int cg = (tid & 7) << 2;    // c offset (floats) 0..28
#pragma unroll
    for (int r = 0; r < 4; ++r) {
        int p = (tid >> 3) + (r << 5);
        const float* b0 = g_xt + gs.gofs[r][0] + c0 + cg;
        const float* b1 = g_xt + gs.gofs[r][1] + c0 + cg;
        const float* b2 = g_xt + gs.gofs[r][2] + c0 + cg;
        const float* b3 = g_xt + gs.gofs[r][3] + c0 + cg;
        float4 v0 = *(const float4*)b0;
        float4 v1 = *(const float4*)b1;
        float4 v2 = *(const float4*)b2;
        float4 v3 = *(const float4*)b3;
        float w0 = gs.wgt[r][0], w1 = gs.wgt[r][1];
        float w2 = gs.wgt[r][2], w3 = gs.wgt[r][3];
        float4 a;
        a.x = __uint_as_float(f2tf32(w0*v0.x + w1*v1.x + w2*v2.x + w3*v3.x));
        a.y = __uint_as_float(f2tf32(w0*v0.y + w1*v1.y + w2*v2.y + w3*v3.y));
        a.z = __uint_as_float(f2tf32(w0*v0.z + w1*v1.z + w2*v2.z + w3*v3.z));
        a.w = __uint_as_float(f2tf32(w0*v0.w + w1*v1.w + w2*v2.w + w3*v3.w));
        *(float4*)(As + p * ROWP + cg) = a;
    }

    // B tile: 128 oc x 32 c from g_wt2 (already tf32-rounded)
    const float* wp = g_wt2 + ((size_t)k * OC + ocb) * CC + c0;
#pragma unroll
    for (int r = 0; r < 4; ++r) {
        int idx = tid + (r << 8);      // 0..1023
        int oc  = idx >> 3;
        int cc  = (idx & 7) << 2;
        *(float4*)(Bs + oc * ROWP + cc) = *(const float4*)(wp + oc * CC + cc);
    }
}

__global__ __launch_bounds__(256)
void k_dconv_mma(const float* __restrict__ offset, float* __restrict__ out)
{
    extern __shared__ float sm[];
    float* Asb[2] = { sm,             sm + TILEF };
    float* Bsb[2] = { sm + 2 * TILEF, sm + 3 * TILEF };

    const int tid  = threadIdx.x;
    const int lane = tid & 31;
    const int wid  = tid >> 5;
    const int bx   = blockIdx.x;
    const int ntile = bx & 1;
    const int mtile = (bx >> 1) & 31;
    const int n     = bx >> 6;
    const int mb    = mtile << 7;
    const int ocb   = ntile << 7;

    const int wm  = (wid & 3) << 5;    // warp M offset 0..96
    const int wn  = (wid >> 2) << 6;   // warp N offset 0/64
    const int gid = lane >> 2;
    const int tig = lane & 3;

    float acc[2][8][4];
#pragma unroll
    for (int mi = 0; mi < 2; ++mi)
#pragma unroll
        for (int ni = 0; ni < 8; ++ni)
#pragma unroll
            for (int q = 0; q < 4; ++q) acc[mi][ni][q] = 0.0f;

    GatherState gs;
    build_tiles(0, tid, n, mb, ocb, offset, Asb[0], Bsb[0], gs);
    __syncthreads();

    for (int i = 0; i < NCHUNK; ++i) {
        if (i + 1 < NCHUNK)
            build_tiles(i + 1, tid, n, mb, ocb, offset,
                        Asb[(i + 1) & 1], Bsb[(i + 1) & 1], gs);

        const float* A = Asb[i & 1];
        const float* B = Bsb[i & 1];
#pragma unroll
        for (int kk = 0; kk < 4; ++kk) {
            const int cb = kk << 3;
            uint32_t a[2][4];
#pragma unroll
            for (int mi = 0; mi < 2; ++mi) {
                int rb = wm + (mi << 4);
                a[mi][0] = __float_as_uint(A[(rb + gid)     * ROWP + cb + tig]);
                a[mi][1] = __float_as_uint(A[(rb + gid + 8) * ROWP + cb + tig]);
                a[mi][2] = __float_as_uint(A[(rb + gid)     * ROWP + cb + tig + 4]);
                a[mi][3] = __float_as_uint(A[(rb + gid + 8) * ROWP + cb + tig + 4]);
            }
#pragma unroll
            for (int ni = 0; ni < 8; ++ni) {
                int col = wn + (ni << 3) + gid;
                uint32_t b0 = __float_as_uint(B[col * ROWP + cb + tig]);
                uint32_t b1 = __float_as_uint(B[col * ROWP + cb + tig + 4]);
#pragma unroll
                for (int mi = 0; mi < 2; ++mi) {
                    asm volatile(
                        "mma.sync.aligned.m16n8k8.row.col.f32.tf32.tf32.f32 "
                        "{%0,%1,%2,%3}, {%4,%5,%6,%7}, {%8,%9}, {%0,%1,%2,%3};"
                        : "+f"(acc[mi][ni][0]), "+f"(acc[mi][ni][1]),
                          "+f"(acc[mi][ni][2]), "+f"(acc[mi][ni][3])
                        : "r"(a[mi][0]), "r"(a[mi][1]), "r"(a[mi][2]), "r"(a[mi][3]),
                          "r"(b0), "r"(b1));
                }
            }
        }
        __syncthreads();
    }

    // ---- epilogue: stage tile [oc][m] (stride 132) then coalesced stores ----
    float* st = sm;                    // 128*132 floats = 67584 B, fits
#pragma unroll
    for (int mi = 0; mi < 2; ++mi) {
        int m0 = wm + (mi << 4) + gid;
#pragma unroll
        for (int ni = 0; ni < 8; ++ni) {
            int c0o = wn + (ni << 3) + (tig << 1);
            st[ c0o      * 132 + m0    ] = acc[mi][ni][0];
            st[(c0o + 1) * 132 + m0    ] = acc[mi][ni][1];
            st[ c0o      * 132 + m0 + 8] = acc[mi][ni][2];
            st[(c0o + 1) * 132 + m0 + 8] = acc[mi][ni][3];
        }
    }
    __syncthreads();

    float* ob = out + ((size_t)n * OC + ocb) * PIX + mb;
#pragma unroll
    for (int r = 0; r < 16; ++r) {
        int idx = tid + (r << 8);      // 0..4095 over 128 oc x 32 float4
        int oc  = idx >> 5;
        int m4  = (idx & 31) << 2;
        *(float4*)(ob + (size_t)oc * PIX + m4) = *(const float4*)(st + oc * 132 + m4);
    }
}

// ---------------------------------------------------------------------------
extern "C" void kernel_launch(void* const* d_in, const int* in_sizes, int n_in,
                              void* d_out, int out_size)
{
    const float* x      = (const float*)d_in[0];   // (8,256,64,64)
    const float* offset = (const float*)d_in[1];   // (8,18,64,64)
    const float* weight = (const float*)d_in[2];   // (256,256,3,3)
    float* out = (float*)d_out;                    // (8,256,64,64)

    const int dyn_smem = 4 * TILEF * sizeof(float);   // 73728 B
    cudaFuncSetAttribute(k_dconv_mma,
                         cudaFuncAttributeMaxDynamicSharedMemorySize, dyn_smem);

    k_transpose_x<<<dim3(PIX / 32, CC / 32, NN), dim3(32, 32)>>>(x);
    k_transpose_w<<<(KK * OC * CC) / 256, 256>>>(weight);
    k_dconv_mma<<<512, 256, dyn_smem>>>(offset, out);
}

// round 5
// speedup vs baseline: 1.8818x; 1.5489x over previous
#include <cuda_runtime.h>
#include <cstdint>

// Problem constants
#define NN   8
#define CC   256
#define HH   64
#define WW   64
#define OC   256
#define KK   9
#define PIX  4096

// Scratch
__device__ float g_xt[NN * PIX * CC];    // x as NHWC [n][h][w][c]
__device__ float g_wt2[KK * OC * CC];    // weights as [k][oc][c], tf32-rounded

__device__ __forceinline__ uint32_t f2tf32(float x) {
    uint32_t r;
    asm("cvt.rna.tf32.f32 %0, %1;" : "=r"(r) : "f"(x));
    return r;
}

// ---------------------------------------------------------------------------
// Kernel 1: NCHW -> NHWC transpose, vectorized both sides.
// grid (PIX/32, CC/32, NN), block 256. Each block: 32 pix x 32 c tile.
// ---------------------------------------------------------------------------
__global__ void k_transpose_x(const float* __restrict__ x)
{
    __shared__ float tile[32 * 33];
    const int n  = blockIdx.z;
    const int p0 = blockIdx.x * 32;
    const int c0 = blockIdx.y * 32;
    const int t  = threadIdx.x;

    {   // read: float4 along pixels
        int c  = t >> 3;
        int p4 = (t & 7) << 2;
        float4 v = *(const float4*)&x[((size_t)(n * CC + c0 + c)) * PIX + p0 + p4];
        tile[c * 33 + p4 + 0] = v.x;
        tile[c * 33 + p4 + 1] = v.y;
        tile[c * 33 + p4 + 2] = v.z;
        tile[c * 33 + p4 + 3] = v.w;
    }
    __syncthreads();
    {   // write: float4 along channels
        int p  = t >> 3;
        int c4 = (t & 7) << 2;
        float4 o;
        o.x = tile[(c4 + 0) * 33 + p];
        o.y = tile[(c4 + 1) * 33 + p];
        o.z = tile[(c4 + 2) * 33 + p];
        o.w = tile[(c4 + 3) * 33 + p];
        *(float4*)&g_xt[((size_t)(n * PIX + p0 + p)) * CC + c0 + c4] = o;
    }
}

// ---------------------------------------------------------------------------
// Kernel 2: weight [oc][c][k] -> [k][oc][c], rounded to tf32
// ---------------------------------------------------------------------------
__global__ void k_transpose_w(const float* __restrict__ w)
{
    int idx = blockIdx.x * 256 + threadIdx.x;
    int c  = idx & 255;
    int oc = (idx >> 8) & 255;
    int k  = idx >> 16;
    g_wt2[idx] = __uint_as_float(f2tf32(w[((size_t)oc * CC + c) * KK + k]));
}

// ---------------------------------------------------------------------------
// Kernel 3: fused deformable gather + tf32 mma GEMM
// CTA: 512 threads, tile M=128 pix x N=128 oc x BK=32.
// 16 warps in 4(M) x 4(N); warp tile 32x32; acc 32 regs/thread.
// Fragment k uses the "identical logical-k permutation" so each thread's
// per-chunk A/B fragments are 8 contiguous floats -> LDS.128.
// grid 512 = 8 n * 32 mtiles * 2 ntiles.
// ---------------------------------------------------------------------------
#define ROWP   36
#define TILEF  (128 * ROWP)
#define NCHUNK 72

__device__ __forceinline__ void build_tiles(
    int i, int tid, int n, int mb, int ocb,
    const float* __restrict__ offset,
    float* __restrict__ As, float* __restrict__ Bs,
    float (*s_gw)[128], int (*s_go)[128])
{
    const int k  = i >> 3;
    const int c0 = (i & 7) << 5;
    const int prow = tid >> 3;          // 0..63
    const int cg4  = (tid & 7) << 2;    // 0..28

    if ((i & 7) == 0) {
        // new k-tap: recompute bilinear params (redundant x8, identical values)
        const int ky = k / 3 - 1, kx = k - (k / 3) * 3 - 1;
        const float* offbase = offset + (size_t)(n * 18 + 2 * k) * PIX + mb;
#pragma unroll
        for (int r = 0; r < 2; ++r) {
            int p  = prow + (r << 6);
            int oh = (mb + p) >> 6, ow = (mb + p) & 63;
            float y  = (float)(oh + ky) + offbase[p];
            float xx = (float)(ow + kx) + offbase[p + PIX];
            float y0 = floorf(y), x0 = floorf(xx);
#pragma unroll
            for (int d = 0; d < 4; ++d) {
                float yi = y0 + (float)(d >> 1);
                float xi = x0 + (float)(d & 1);
                float wv = (1.0f - fabsf(y - yi)) * (1.0f - fabsf(xx - xi));
                bool valid = (yi >= 0.0f) && (yi <= 63.0f) &&
                             (xi >= 0.0f) && (xi <= 63.0f);
                int yc = (int)fminf(fmaxf(yi, 0.0f), 63.0f);
                int xc = (int)fminf(fmaxf(xi, 0.0f), 63.0f);
                s_gw[d][p] = valid ? wv : 0.0f;
                s_go[d][p] = ((n * HH + yc) * WW + xc) << 8;
            }
        }
    }

    // A tile: bilinear gather + tf32 convert (2 rows per thread)
#pragma unroll
    for (int r = 0; r < 2; ++r) {
        int p = prow + (r << 6);
        float w0 = s_gw[0][p], w1 = s_gw[1][p], w2 = s_gw[2][p], w3 = s_gw[3][p];
        const float* b0 = g_xt + s_go[0][p] + c0 + cg4;
        const float* b1 = g_xt + s_go[1][p] + c0 + cg4;
        const float* b2 = g_xt + s_go[2][p] + c0 + cg4;
        const float* b3 = g_xt + s_go[3][p] + c0 + cg4;
        float4 v0 = *(const float4*)b0;
        float4 v1 = *(const float4*)b1;
        float4 v2 = *(const float4*)b2;
        float4 v3 = *(const float4*)b3;
        float4 a;
        a.x = __uint_as_float(f2tf32(w0*v0.x + w1*v1.x + w2*v2.x + w3*v3.x));
        a.y = __uint_as_float(f2tf32(w0*v0.y + w1*v1.y + w2*v2.y + w3*v3.y));
        a.z = __uint_as_float(f2tf32(w0*v0.z + w1*v1.z + w2*v2.z + w3*v3.z));
        a.w = __uint_as_float(f2tf32(w0*v0.w + w1*v1.w + w2*v2.w + w3*v3.w));
        *(float4*)(As + p * ROWP + cg4) = a;
    }

    // B tile: 128 oc x 32 c (2 float4 per thread)
#pragma unroll
    for (int r = 0; r < 2; ++r) {
        int idx = tid + (r << 9);
        int oc  = idx >> 3;
        int cf  = (idx & 7) << 2;
        *(float4*)(Bs + oc * ROWP + cf) =
            *(const float4*)(g_wt2 + ((size_t)k * OC + ocb + oc) * CC + c0 + cf);
    }
}

__global__ __launch_bounds__(512, 1)
void k_dconv_mma(const float* __restrict__ offset, float* __restrict__ out)
{
    extern __shared__ float sm[];
    __shared__ float s_gw[4][128];
    __shared__ int   s_go[4][128];

    float* Asb[2] = { sm,             sm + TILEF };
    float* Bsb[2] = { sm + 2 * TILEF, sm + 3 * TILEF };

    const int tid  = threadIdx.x;
    const int lane = tid & 31;
    const int wid  = tid >> 5;
    const int bx   = blockIdx.x;
    const int ntile = bx & 1;
    const int mtile = (bx >> 1) & 31;
    const int n     = bx >> 6;
    const int mb    = mtile << 7;
    const int ocb   = ntile << 7;

    const int wm  = (wid & 3) << 5;     // 0,32,64,96
    const int wn  = (wid >> 2) << 5;    // 0,32,64,96
    const int gid = lane >> 2;
    const int tig = lane & 3;

    float acc[2][4][4];
#pragma unroll
    for (int mi = 0; mi < 2; ++mi)
#pragma unroll
        for (int ni = 0; ni < 4; ++ni)
#pragma unroll
            for (int q = 0; q < 4; ++q) acc[mi][ni][q] = 0.0f;

    build_tiles(0, tid, n, mb, ocb, offset, Asb[0], Bsb[0], s_gw, s_go);
    __syncthreads();

    for (int i = 0; i < NCHUNK; ++i) {
        if (i + 1 < NCHUNK)
            build_tiles(i + 1, tid, n, mb, ocb, offset,
                        Asb[(i + 1) & 1], Bsb[(i + 1) & 1], s_gw, s_go);

        const float* A = Asb[i & 1];
        const float* B = Bsb[i & 1];

        // fragment loads: 8 contiguous floats per row/col (2x LDS.128 each)
        float a_r[4][8];
#pragma unroll
        for (int j = 0; j < 4; ++j) {
            const float* src = A + (wm + (j << 3) + gid) * ROWP + (tig << 3);
            *(float4*)&a_r[j][0] = *(const float4*)(src);
            *(float4*)&a_r[j][4] = *(const float4*)(src + 4);
        }
        float b_r[4][8];
#pragma unroll
        for (int j = 0; j < 4; ++j) {
            const float* src = B + (wn + (j << 3) + gid) * ROWP + (tig << 3);
            *(float4*)&b_r[j][0] = *(const float4*)(src);
            *(float4*)&b_r[j][4] = *(const float4*)(src + 4);
        }

#pragma unroll
        for (int kk = 0; kk < 4; ++kk) {
#pragma unroll
            for (int mi = 0; mi < 2; ++mi) {
                uint32_t a0 = __float_as_uint(a_r[2*mi  ][2*kk]);
                uint32_t a1 = __float_as_uint(a_r[2*mi+1][2*kk]);
                uint32_t a2 = __float_as_uint(a_r[2*mi  ][2*kk+1]);
                uint32_t a3 = __float_as_uint(a_r[2*mi+1][2*kk+1]);
#pragma unroll
                for (int ni = 0; ni < 4; ++ni) {
                    uint32_t b0 = __float_as_uint(b_r[ni][2*kk]);
                    uint32_t b1 = __float_as_uint(b_r[ni][2*kk+1]);
                    asm volatile(
                        "mma.sync.aligned.m16n8k8.row.col.f32.tf32.tf32.f32 "
                        "{%0,%1,%2,%3}, {%4,%5,%6,%7}, {%8,%9}, {%0,%1,%2,%3};"
                        : "+f"(acc[mi][ni][0]), "+f"(acc[mi][ni][1]),
                          "+f"(acc[mi][ni][2]), "+f"(acc[mi][ni][3])
                        : "r"(a0), "r"(a1), "r"(a2), "r"(a3), "r"(b0), "r"(b1));
                }
            }
        }
        __syncthreads();
    }

    // ---- epilogue: stage [oc][m] (pitch 132), then coalesced stores ----
    float* st = sm;     // 128*132*4 = 67.6 KB <= 73.7 KB
#pragma unroll
    for (int mi = 0; mi < 2; ++mi) {
        int row0 = wm + (mi << 4) + gid;
#pragma unroll
        for (int ni = 0; ni < 4; ++ni) {
            int col = wn + (ni << 3) + (tig << 1);
            st[ col      * 132 + row0    ] = acc[mi][ni][0];
            st[(col + 1) * 132 + row0    ] = acc[mi][ni][1];
            st[ col      * 132 + row0 + 8] = acc[mi][ni][2];
            st[(col + 1) * 132 + row0 + 8] = acc[mi][ni][3];
        }
    }
    __syncthreads();

    float* ob = out + ((size_t)n * OC + ocb) * PIX + mb;
#pragma unroll
    for (int it = 0; it < 8; ++it) {
        int idx = tid + (it << 9);          // 0..4095 over 128 oc x 32 float4
        int oc  = idx >> 5;
        int m4  = (idx & 31) << 2;
        *(float4*)(ob + (size_t)oc * PIX + m4) = *(const float4*)(st + oc * 132 + m4);
    }
}

// ---------------------------------------------------------------------------
extern "C" void kernel_launch(void* const* d_in, const int* in_sizes, int n_in,
                              void* d_out, int out_size)
{
    const float* x      = (const float*)d_in[0];   // (8,256,64,64)
    const float* offset = (const float*)d_in[1];   // (8,18,64,64)
    const float* weight = (const float*)d_in[2];   // (256,256,3,3)
    float* out = (float*)d_out;                    // (8,256,64,64)

    const int dyn_smem = 4 * TILEF * sizeof(float);   // 73728 B
    cudaFuncSetAttribute(k_dconv_mma,
                         cudaFuncAttributeMaxDynamicSharedMemorySize, dyn_smem);

    k_transpose_x<<<dim3(PIX / 32, CC / 32, NN), 256>>>(x);
    k_transpose_w<<<(KK * OC * CC) / 256, 256>>>(weight);
    k_dconv_mma<<<512, 512, dyn_smem>>>(offset, out);
}

// round 6
// speedup vs baseline: 2.4927x; 1.3246x over previous
#include <cuda_runtime.h>
#include <cstdint>

// Problem constants
#define NN   8
#define CC   256
#define HH   64
#define WW   64
#define OC   256
#define KK   9
#define PIX  4096

// Scratch
__device__ float g_xt[NN * PIX * CC];    // x as NHWC [n][h][w][c]
__device__ float g_wt2[KK * OC * CC];    // weights as [k][oc][c], tf32-rounded

__device__ __forceinline__ uint32_t f2tf32(float x) {
    uint32_t r;
    asm("cvt.rna.tf32.f32 %0, %1;" : "=r"(r) : "f"(x));
    return r;
}

// ---------------------------------------------------------------------------
// Kernel 1: NCHW -> NHWC transpose, vectorized both sides.
// ---------------------------------------------------------------------------
__global__ void k_transpose_x(const float* __restrict__ x)
{
    __shared__ float tile[32 * 33];
    const int n  = blockIdx.z;
    const int p0 = blockIdx.x * 32;
    const int c0 = blockIdx.y * 32;
    const int t  = threadIdx.x;

    {
        int c  = t >> 3;
        int p4 = (t & 7) << 2;
        float4 v = *(const float4*)&x[((size_t)(n * CC + c0 + c)) * PIX + p0 + p4];
        tile[c * 33 + p4 + 0] = v.x;
        tile[c * 33 + p4 + 1] = v.y;
        tile[c * 33 + p4 + 2] = v.z;
        tile[c * 33 + p4 + 3] = v.w;
    }
    __syncthreads();
    {
        int p  = t >> 3;
        int c4 = (t & 7) << 2;
        float4 o;
        o.x = tile[(c4 + 0) * 33 + p];
        o.y = tile[(c4 + 1) * 33 + p];
        o.z = tile[(c4 + 2) * 33 + p];
        o.w = tile[(c4 + 3) * 33 + p];
        *(float4*)&g_xt[((size_t)(n * PIX + p0 + p)) * CC + c0 + c4] = o;
    }
}

// ---------------------------------------------------------------------------
// Kernel 2: weight [oc][c][k] -> [k][oc][c], rounded to tf32
// ---------------------------------------------------------------------------
__global__ void k_transpose_w(const float* __restrict__ w)
{
    int idx = blockIdx.x * 256 + threadIdx.x;
    int c  = idx & 255;
    int oc = (idx >> 8) & 255;
    int k  = idx >> 16;
    g_wt2[idx] = __uint_as_float(f2tf32(w[((size_t)oc * CC + c) * KK + k]));
}

// ---------------------------------------------------------------------------
// Kernel 3: fused deformable gather + tf32 mma GEMM
// CTA: 512 threads, tile M=128 pix x N=256 oc x BK=32.
// 16 warps in 4(M) x 4(N); warp tile 32x64; acc 64 regs/thread.
// B fragments loaded per-ni (LDS.128 x2 feeding 8 mma).
// grid 256 = 8 n * 32 mtiles.
// ---------------------------------------------------------------------------
#define ROWP    36
#define TILEA   (128 * ROWP)          // 4608 floats
#define TILEB   (256 * ROWP)          // 9216 floats
#define NCHUNK  72

__device__ __forceinline__ void cp_async16(uint32_t saddr, const void* g) {
    asm volatile("cp.async.cg.shared.global [%0], [%1], 16;"
                 :: "r"(saddr), "l"(g) : "memory");
}

__device__ __forceinline__ void build_tiles(
    int i, int tid, int n, int mb,
    const float* __restrict__ offset,
    float* __restrict__ As, float* __restrict__ Bs,
    float (*s_gw)[128], int (*s_go)[128])
{
    const int k  = i >> 3;
    const int c0 = (i & 7) << 5;
    const int prow = tid >> 3;          // 0..63
    const int cg4  = (tid & 7) << 2;    // 0..28

    // B tile: 256 oc x 32 c, via cp.async (no register staging)
    {
        const float* wb = g_wt2 + (size_t)k * OC * CC + c0;
        uint32_t bbase = (uint32_t)__cvta_generic_to_shared(Bs);
#pragma unroll
        for (int r = 0; r < 4; ++r) {
            int idx = tid + (r << 9);
            int oc  = idx >> 3;
            int cf  = (idx & 7) << 2;
            cp_async16(bbase + (uint32_t)(oc * ROWP + cf) * 4,
                       wb + (size_t)oc * CC + cf);
        }
    }

    if ((i & 7) == 0) {
        const int ky = k / 3 - 1, kx = k - (k / 3) * 3 - 1;
        const float* offbase = offset + (size_t)(n * 18 + 2 * k) * PIX + mb;
#pragma unroll
        for (int r = 0; r < 2; ++r) {
            int p  = prow + (r << 6);
            int oh = (mb + p) >> 6, ow = (mb + p) & 63;
            float y  = (float)(oh + ky) + offbase[p];
            float xx = (float)(ow + kx) + offbase[p + PIX];
            float y0 = floorf(y), x0 = floorf(xx);
#pragma unroll
            for (int d = 0; d < 4; ++d) {
                float yi = y0 + (float)(d >> 1);
                float xi = x0 + (float)(d & 1);
                float wv = (1.0f - fabsf(y - yi)) * (1.0f - fabsf(xx - xi));
                bool valid = (yi >= 0.0f) && (yi <= 63.0f) &&
                             (xi >= 0.0f) && (xi <= 63.0f);
                int yc = (int)fminf(fmaxf(yi, 0.0f), 63.0f);
                int xc = (int)fminf(fmaxf(xi, 0.0f), 63.0f);
                s_gw[d][p] = valid ? wv : 0.0f;
                s_go[d][p] = ((n * HH + yc) * WW + xc) << 8;
            }
        }
    }

    // A tile: bilinear gather + tf32 convert (2 rows per thread)
#pragma unroll
    for (int r = 0; r < 2; ++r) {
        int p = prow + (r << 6);
        float w0 = s_gw[0][p], w1 = s_gw[1][p], w2 = s_gw[2][p], w3 = s_gw[3][p];
        const float* b0 = g_xt + s_go[0][p] + c0 + cg4;
        const float* b1 = g_xt + s_go[1][p] + c0 + cg4;
        const float* b2 = g_xt + s_go[2][p] + c0 + cg4;
        const float* b3 = g_xt + s_go[3][p] + c0 + cg4;
        float4 v0 = *(const float4*)b0;
        float4 v1 = *(const float4*)b1;
        float4 v2 = *(const float4*)b2;
        float4 v3 = *(const float4*)b3;
        float4 a;
        a.x = __uint_as_float(f2tf32(w0*v0.x + w1*v1.x + w2*v2.x + w3*v3.x));
        a.y = __uint_as_float(f2tf32(w0*v0.y + w1*v1.y + w2*v2.y + w3*v3.y));
        a.z = __uint_as_float(f2tf32(w0*v0.z + w1*v1.z + w2*v2.z + w3*v3.z));
        a.w = __uint_as_float(f2tf32(w0*v0.w + w1*v1.w + w2*v2.w + w3*v3.w));
        *(float4*)(As + p * ROWP + cg4) = a;
    }
}

__global__ __launch_bounds__(512, 1)
void k_dconv_mma(const float* __restrict__ offset, float* __restrict__ out)
{
    extern __shared__ float sm[];
    __shared__ float s_gw[4][128];
    __shared__ int   s_go[4][128];

    float* Asb[2] = { sm,             sm + TILEA };
    float* Bsb[2] = { sm + 2 * TILEA, sm + 2 * TILEA + TILEB };

    const int tid  = threadIdx.x;
    const int lane = tid & 31;
    const int wid  = tid >> 5;
    const int bx   = blockIdx.x;
    const int n    = bx >> 5;
    const int mb   = (bx & 31) << 7;

    const int wm  = (wid & 3) << 5;     // 0,32,64,96
    const int wn  = (wid >> 2) << 6;    // 0,64,128,192
    const int gid = lane >> 2;
    const int tig = lane & 3;

    float acc[2][8][4];
#pragma unroll
    for (int mi = 0; mi < 2; ++mi)
#pragma unroll
        for (int ni = 0; ni < 8; ++ni)
#pragma unroll
            for (int q = 0; q < 4; ++q) acc[mi][ni][q] = 0.0f;

    build_tiles(0, tid, n, mb, offset, Asb[0], Bsb[0], s_gw, s_go);
    asm volatile("cp.async.wait_all;" ::: "memory");
    __syncthreads();

    for (int i = 0; i < NCHUNK; ++i) {
        if (i + 1 < NCHUNK)
            build_tiles(i + 1, tid, n, mb, offset,
                        Asb[(i + 1) & 1], Bsb[(i + 1) & 1], s_gw, s_go);

        const float* A = Asb[i & 1];
        const float* B = Bsb[i & 1];

        // A fragments: 8 contiguous floats per row (k-permuted layout)
        float a_r[4][8];
#pragma unroll
        for (int j = 0; j < 4; ++j) {
            const float* src = A + (wm + (j << 3) + gid) * ROWP + (tig << 3);
            *(float4*)&a_r[j][0] = *(const float4*)(src);
            *(float4*)&a_r[j][4] = *(const float4*)(src + 4);
        }

#pragma unroll
        for (int ni = 0; ni < 8; ++ni) {
            float b_r[8];
            const float* src = B + (wn + (ni << 3) + gid) * ROWP + (tig << 3);
            *(float4*)&b_r[0] = *(const float4*)(src);
            *(float4*)&b_r[4] = *(const float4*)(src + 4);
#pragma unroll
            for (int kk = 0; kk < 4; ++kk) {
                uint32_t b0 = __float_as_uint(b_r[2*kk]);
                uint32_t b1 = __float_as_uint(b_r[2*kk+1]);
#pragma unroll
                for (int mi = 0; mi < 2; ++mi) {
                    uint32_t a0 = __float_as_uint(a_r[2*mi  ][2*kk]);
                    uint32_t a1 = __float_as_uint(a_r[2*mi+1][2*kk]);
                    uint32_t a2 = __float_as_uint(a_r[2*mi  ][2*kk+1]);
                    uint32_t a3 = __float_as_uint(a_r[2*mi+1][2*kk+1]);
                    asm volatile(
                        "mma.sync.aligned.m16n8k8.row.col.f32.tf32.tf32.f32 "
                        "{%0,%1,%2,%3}, {%4,%5,%6,%7}, {%8,%9}, {%0,%1,%2,%3};"
                        : "+f"(acc[mi][ni][0]), "+f"(acc[mi][ni][1]),
                          "+f"(acc[mi][ni][2]), "+f"(acc[mi][ni][3])
                        : "r"(a0), "r"(a1), "r"(a2), "r"(a3), "r"(b0), "r"(b1));
                }
            }
        }
        asm volatile("cp.async.wait_all;" ::: "memory");
        __syncthreads();
    }

    // ---- epilogue: two 128-oc halves staged [oc][m] (pitch 132) ----
    float* st = sm;     // 128*132*4 = 67.6 KB <= 110.6 KB dyn
#pragma unroll
    for (int h = 0; h < 2; ++h) {
        __syncthreads();
        if ((wn >> 7) == h) {
            int wnl = wn & 127;
#pragma unroll
            for (int mi = 0; mi < 2; ++mi) {
                int row0 = wm + (mi << 4) + gid;
#pragma unroll
                for (int ni = 0; ni < 8; ++ni) {
                    int col = wnl + (ni << 3) + (tig << 1);
                    st[ col      * 132 + row0    ] = acc[mi][ni][0];
                    st[(col + 1) * 132 + row0    ] = acc[mi][ni][1];
                    st[ col      * 132 + row0 + 8] = acc[mi][ni][2];
                    st[(col + 1) * 132 + row0 + 8] = acc[mi][ni][3];
                }
            }
        }
        __syncthreads();
        float* ob = out + ((size_t)n * OC + h * 128) * PIX + mb;
#pragma unroll
        for (int it = 0; it < 8; ++it) {
            int idx = tid + (it << 9);       // 0..4095 over 128 oc x 32 float4
            int oc  = idx >> 5;
            int m4  = (idx & 31) << 2;
            *(float4*)(ob + (size_t)oc * PIX + m4) =
                *(const float4*)(st + oc * 132 + m4);
        }
    }
}

// ---------------------------------------------------------------------------
extern "C" void kernel_launch(void* const* d_in, const int* in_sizes, int n_in,
                              void* d_out, int out_size)
{
    const float* x      = (const float*)d_in[0];   // (8,256,64,64)
    const float* offset = (const float*)d_in[1];   // (8,18,64,64)
    const float* weight = (const float*)d_in[2];   // (256,256,3,3)
    float* out = (float*)d_out;                    // (8,256,64,64)

    const int dyn_smem = (2 * TILEA + 2 * TILEB) * sizeof(float);   // 110592 B
    cudaFuncSetAttribute(k_dconv_mma,
                         cudaFuncAttributeMaxDynamicSharedMemorySize, dyn_smem);

    k_transpose_x<<<dim3(PIX / 32, CC / 32, NN), 256>>>(x);
    k_transpose_w<<<(KK * OC * CC) / 256, 256>>>(weight);
    k_dconv_mma<<<256, 512, dyn_smem>>>(offset, out);
}

// round 7
// speedup vs baseline: 2.8233x; 1.1326x over previous
#include <cuda_runtime.h>
#include <cuda_fp16.h>
#include <cstdint>

// Problem constants
#define NN   8
#define CC   256
#define HH   64
#define WW   64
#define OC   256
#define KK   9
#define PIX  4096

// Scratch
__device__ float  g_xt[NN * PIX * CC];      // x as NHWC [n][h][w][c], fp32
__device__ __half g_wh[72 * OC * 32];       // weights fp16, [chunk][oc][32 sigma-permuted]

// sigma: logical l (0..31) <-> physical p: p = t*8 + kk*4 + h*2 + b
// where l = kk*16 + 2t + b + 8h  (t=0..3, kk,h,b in {0,1})

__device__ __forceinline__ void cp_async16(uint32_t saddr, const void* g) {
    asm volatile("cp.async.cg.shared.global [%0], [%1], 16;"
                 :: "r"(saddr), "l"(g) : "memory");
}

// ---------------------------------------------------------------------------
// Kernel 1: NCHW -> NHWC transpose, vectorized both sides.
// ---------------------------------------------------------------------------
__global__ void k_transpose_x(const float* __restrict__ x)
{
    __shared__ float tile[32 * 33];
    const int n  = blockIdx.z;
    const int p0 = blockIdx.x * 32;
    const int c0 = blockIdx.y * 32;
    const int t  = threadIdx.x;
    {
        int c  = t >> 3;
        int p4 = (t & 7) << 2;
        float4 v = *(const float4*)&x[((size_t)(n * CC + c0 + c)) * PIX + p0 + p4];
        tile[c * 33 + p4 + 0] = v.x;
        tile[c * 33 + p4 + 1] = v.y;
        tile[c * 33 + p4 + 2] = v.z;
        tile[c * 33 + p4 + 3] = v.w;
    }
    __syncthreads();
    {
        int p  = t >> 3;
        int c4 = (t & 7) << 2;
        float4 o;
        o.x = tile[(c4 + 0) * 33 + p];
        o.y = tile[(c4 + 1) * 33 + p];
        o.z = tile[(c4 + 2) * 33 + p];
        o.w = tile[(c4 + 3) * 33 + p];
        *(float4*)&g_xt[((size_t)(n * PIX + p0 + p)) * CC + c0 + c4] = o;
    }
}

// ---------------------------------------------------------------------------
// Kernel 2: weight [oc][c][k] -> fp16 [chunk72][oc][32 phys], sigma-permuted
// ---------------------------------------------------------------------------
__global__ void k_prep_w(const float* __restrict__ w)
{
    int idx = blockIdx.x * 256 + threadIdx.x;   // over 72*256*32
    int p   = idx & 31;
    int oc  = (idx >> 5) & 255;
    int ch  = idx >> 13;                        // chunk 0..71
    int k   = ch >> 3;
    int c0  = (ch & 7) << 5;
    int t  = p >> 3, q = p & 7;
    int kk = q >> 2, h = (q >> 1) & 1, b = q & 1;
    int l  = kk * 16 + 2 * t + b + 8 * h;
    g_wh[idx] = __float2half_rn(w[((size_t)oc * CC + c0 + l) * KK + k]);
}

// ---------------------------------------------------------------------------
// Kernel 3: fused deformable gather + fp16 m16n8k16 mma GEMM
// CTA: 512 threads, tile M=128 x N=256 x BK=32; 16 warps 4(M)x4(N), warp 32x64
// grid 256 = 8 n * 32 mtiles.
// ---------------------------------------------------------------------------
#define NCHUNK 72
#define AHALF  (128 * 32)     // halfs per A buffer
#define BHALF  (256 * 32)

__device__ __forceinline__ void build_tiles(
    int i, int tid, int n, int mb,
    const float* __restrict__ offset,
    __half* __restrict__ As, __half* __restrict__ Bs,
    float* gw, int* go)
{
    const int k   = i >> 3;
    const int c0  = (i & 7) << 5;
    const int row = tid >> 2;        // 0..127 (pixel within tile)
    const int u   = tid & 3;         // logical c-group (8 c each)

    // B tile via cp.async: 256 oc x 64 B (pre-permuted fp16)
    {
        const __half* wb = g_wh + (size_t)i * (OC * 32);
        uint32_t bbase = (uint32_t)__cvta_generic_to_shared(Bs);
#pragma unroll
        for (int r = 0; r < 2; ++r) {
            int idx = tid + (r << 9);               // 0..1023 16B chunks
            cp_async16(bbase + (uint32_t)idx * 16, wb + idx * 8);
        }
    }

    if ((i & 7) == 0) {   // new k-tap: recompute private bilinear params
        const int ky = k / 3 - 1, kx = k - (k / 3) * 3 - 1;
        const float* offp = offset + (size_t)(n * 18 + 2 * k) * PIX + mb;
        int oh = (mb + row) >> 6, ow = (mb + row) & 63;
        float y  = (float)(oh + ky) + offp[row];
        float xx = (float)(ow + kx) + offp[row + PIX];
        float y0 = floorf(y), x0 = floorf(xx);
#pragma unroll
        for (int d = 0; d < 4; ++d) {
            float yi = y0 + (float)(d >> 1);
            float xi = x0 + (float)(d & 1);
            float wv = (1.0f - fabsf(y - yi)) * (1.0f - fabsf(xx - xi));
            bool valid = (yi >= 0.0f) && (yi <= 63.0f) &&
                         (xi >= 0.0f) && (xi <= 63.0f);
            int yc = (int)fminf(fmaxf(yi, 0.0f), 63.0f);
            int xc = (int)fminf(fmaxf(xi, 0.0f), 63.0f);
            gw[d] = valid ? wv : 0.0f;
            go[d] = ((n * HH + yc) * WW + xc) << 8;
        }
    }

    // gather 8 contiguous logical c (c0 + u*8 ..), bilinear combine in fp32
    float a[8];
    {
        const float* b0 = g_xt + go[0] + c0 + u * 8;
        const float* b1 = g_xt + go[1] + c0 + u * 8;
        const float* b2 = g_xt + go[2] + c0 + u * 8;
        const float* b3 = g_xt + go[3] + c0 + u * 8;
        float w0 = gw[0], w1 = gw[1], w2 = gw[2], w3 = gw[3];
#pragma unroll
        for (int hlf = 0; hlf < 2; ++hlf) {
            float4 v0 = *(const float4*)(b0 + hlf * 4);
            float4 v1 = *(const float4*)(b1 + hlf * 4);
            float4 v2 = *(const float4*)(b2 + hlf * 4);
            float4 v3 = *(const float4*)(b3 + hlf * 4);
            a[hlf*4+0] = w0*v0.x + w1*v1.x + w2*v2.x + w3*v3.x;
            a[hlf*4+1] = w0*v0.y + w1*v1.y + w2*v2.y + w3*v3.y;
            a[hlf*4+2] = w0*v0.z + w1*v1.z + w2*v2.z + w3*v3.z;
            a[hlf*4+3] = w0*v0.w + w1*v1.w + w2*v2.w + w3*v3.w;
        }
    }
    // sigma-scatter as half2: pair (2jj,2jj+1) -> phys fp16 offset u*2 + jj*8
    // rotation by (row>>1)&3 makes all 4 STS rounds bank-conflict-free
    int jrot = (row >> 1) & 3;
#pragma unroll
    for (int j = 0; j < 4; ++j) {
        int jj = (j + jrot) & 3;
        __half2 hv = __floats2half2_rn(a[2*jj], a[2*jj + 1]);
        *(__half2*)(As + row * 32 + u * 2 + jj * 8) = hv;
    }
}

__global__ __launch_bounds__(512, 1)
void k_dconv_mma(const float* __restrict__ offset, float* __restrict__ out)
{
    extern __shared__ float sm[];
    __half* smh = (__half*)sm;
    __half* Asb[2] = { smh,             smh + AHALF };
    __half* Bsb[2] = { smh + 2 * AHALF, smh + 2 * AHALF + BHALF };

    const int tid  = threadIdx.x;
    const int lane = tid & 31;
    const int wid  = tid >> 5;
    const int bx   = blockIdx.x;
    const int n    = bx >> 5;
    const int mb   = (bx & 31) << 7;

    const int wm  = (wid & 3) << 5;     // 0,32,64,96
    const int wn  = (wid >> 2) << 6;    // 0,64,128,192
    const int gid = lane >> 2;
    const int tig = lane & 3;

    float acc[2][8][4];
#pragma unroll
    for (int mi = 0; mi < 2; ++mi)
#pragma unroll
        for (int ni = 0; ni < 8; ++ni)
#pragma unroll
            for (int q = 0; q < 4; ++q) acc[mi][ni][q] = 0.0f;

    float gw[4]; int go[4];
    build_tiles(0, tid, n, mb, offset, Asb[0], Bsb[0], gw, go);
    asm volatile("cp.async.wait_all;" ::: "memory");
    __syncthreads();

    for (int i = 0; i < NCHUNK; ++i) {
        if (i + 1 < NCHUNK)
            build_tiles(i + 1, tid, n, mb, offset,
                        Asb[(i + 1) & 1], Bsb[(i + 1) & 1], gw, go);

        const __half* A = Asb[i & 1];
        const __half* B = Bsb[i & 1];

        // A fragments: 4 rows x 16B (LDS.128 each)
        uint32_t afr[4][4];
#pragma unroll
        for (int r4 = 0; r4 < 4; ++r4) {
            const uint4 v = *(const uint4*)(A + (wm + gid + r4 * 8) * 32 + tig * 8);
            afr[r4][0] = v.x; afr[r4][1] = v.y; afr[r4][2] = v.z; afr[r4][3] = v.w;
        }

#pragma unroll
        for (int ni = 0; ni < 8; ++ni) {
            const uint4 bv = *(const uint4*)(B + (wn + ni * 8 + gid) * 32 + tig * 8);
            const uint32_t bfr[4] = { bv.x, bv.y, bv.z, bv.w };
#pragma unroll
            for (int kk = 0; kk < 2; ++kk) {
#pragma unroll
                for (int mi = 0; mi < 2; ++mi) {
                    asm volatile(
                        "mma.sync.aligned.m16n8k16.row.col.f32.f16.f16.f32 "
                        "{%0,%1,%2,%3}, {%4,%5,%6,%7}, {%8,%9}, {%0,%1,%2,%3};"
                        : "+f"(acc[mi][ni][0]), "+f"(acc[mi][ni][1]),
                          "+f"(acc[mi][ni][2]), "+f"(acc[mi][ni][3])
                        : "r"(afr[2*mi][2*kk]),   "r"(afr[2*mi+1][2*kk]),
                          "r"(afr[2*mi][2*kk+1]), "r"(afr[2*mi+1][2*kk+1]),
                          "r"(bfr[2*kk]), "r"(bfr[2*kk+1]));
                }
            }
        }
        asm volatile("cp.async.wait_all;" ::: "memory");
        __syncthreads();
    }

    // ---- epilogue: two 128-oc halves staged [oc][m] (pitch 132) ----
    float* st = sm;     // 128*132*4 = 67584 B = dyn smem
#pragma unroll
    for (int h = 0; h < 2; ++h) {
        __syncthreads();
        if ((wn >> 7) == h) {
            int wnl = wn & 127;
#pragma unroll
            for (int mi = 0; mi < 2; ++mi) {
                int row0 = wm + (mi << 4) + gid;
#pragma unroll
                for (int ni = 0; ni < 8; ++ni) {
                    int col = wnl + (ni << 3) + (tig << 1);
                    st[ col      * 132 + row0    ] = acc[mi][ni][0];
                    st[(col + 1) * 132 + row0    ] = acc[mi][ni][1];
                    st[ col      * 132 + row0 + 8] = acc[mi][ni][2];
                    st[(col + 1) * 132 + row0 + 8] = acc[mi][ni][3];
                }
            }
        }
        __syncthreads();
        float* ob = out + ((size_t)n * OC + h * 128) * PIX + mb;
#pragma unroll
        for (int it = 0; it < 8; ++it) {
            int idx = tid + (it << 9);       // 128 oc x 32 float4
            int oc  = idx >> 5;
            int m4  = (idx & 31) << 2;
            *(float4*)(ob + (size_t)oc * PIX + m4) =
                *(const float4*)(st + oc * 132 + m4);
        }
    }
}

// ---------------------------------------------------------------------------
extern "C" void kernel_launch(void* const* d_in, const int* in_sizes, int n_in,
                              void* d_out, int out_size)
{
    const float* x      = (const float*)d_in[0];   // (8,256,64,64)
    const float* offset = (const float*)d_in[1];   // (8,18,64,64)
    const float* weight = (const float*)d_in[2];   // (256,256,3,3)
    float* out = (float*)d_out;                    // (8,256,64,64)

    const int dyn_smem = 128 * 132 * sizeof(float);   // 67584 B (>= tile 49152)
    cudaFuncSetAttribute(k_dconv_mma,
                         cudaFuncAttributeMaxDynamicSharedMemorySize, dyn_smem);

    k_transpose_x<<<dim3(PIX / 32, CC / 32, NN), 256>>>(x);
    k_prep_w<<<(72 * OC * 32) / 256, 256>>>(weight);
    k_dconv_mma<<<256, 512, dyn_smem>>>(offset, out);
}